// round 15
// baseline (speedup 1.0000x reference)
#include <cuda_runtime.h>
#include <cuda_fp16.h>
#include <cstdint>
#include <math.h>

// Problem constants
#define BB 2
#define TT 2048
#define CC 2048
#define HH 16
#define DD 128
#define MM (BB*TT)          // 4096
#define N_QKV (3*CC)        // 6144

// Scratch (static device globals; no runtime allocation allowed)
__device__ float g_invfreq[DD/2];

// fp16 operands
__device__ __half g_xh[(size_t)MM * CC];
__device__ __half g_yh[(size_t)MM * CC];         // attention out [B,T,C]
__device__ __half g_wqt_h[(size_t)N_QKV * CC];   // w_qkv^T [N,K]
__device__ __half g_wot_h[(size_t)CC * CC];      // w_out^T
__device__ __half g_qpre[(size_t)MM * CC];       // pre-rope q [B,H,T,D]
__device__ __half g_kpre[(size_t)MM * CC];       // pre-rope k [B,H,T,D]
__device__ __half g_kh[(size_t)MM * CC];         // roped k [B,H,T,D]
__device__ __half g_vh[(size_t)MM * CC];         // v (from GEMM1 epilogue)

// ===========================================================================
__device__ __forceinline__ uint32_t smem_u32(const void* p) {
    uint32_t a;
    asm("{ .reg .u64 t; cvta.to.shared.u64 t, %1; cvt.u32.u64 %0, t; }"
        : "=r"(a) : "l"(p));
    return a;
}
#define CP_ASYNC16(dst, src) \
    asm volatile("cp.async.cg.shared.global [%0], [%1], 16;" :: "r"(dst), "l"(src))
#define CP_COMMIT() asm volatile("cp.async.commit_group;" ::: "memory")
#define CP_WAIT(n)  asm volatile("cp.async.wait_group %0;" :: "n"(n) : "memory")

__device__ __forceinline__ void ldsm4(uint32_t* r, uint32_t addr) {
    asm volatile("ldmatrix.sync.aligned.m8n8.x4.shared.b16 {%0,%1,%2,%3}, [%4];"
        : "=r"(r[0]), "=r"(r[1]), "=r"(r[2]), "=r"(r[3]) : "r"(addr));
}
__device__ __forceinline__ void ldsm4t(uint32_t* r, uint32_t addr) {
    asm volatile("ldmatrix.sync.aligned.m8n8.x4.trans.shared.b16 {%0,%1,%2,%3}, [%4];"
        : "=r"(r[0]), "=r"(r[1]), "=r"(r[2]), "=r"(r[3]) : "r"(addr));
}
__device__ __forceinline__ void mma_f16(float* d, const uint32_t* a, const uint32_t* b) {
    asm volatile("mma.sync.aligned.m16n8k16.row.col.f32.f16.f16.f32 "
        "{%0,%1,%2,%3}, {%4,%5,%6,%7}, {%8,%9}, {%0,%1,%2,%3};"
        : "+f"(d[0]), "+f"(d[1]), "+f"(d[2]), "+f"(d[3])
        : "r"(a[0]), "r"(a[1]), "r"(a[2]), "r"(a[3]), "r"(b[0]), "r"(b[1]));
}

// ===========================================================================
__global__ void init_invfreq_kernel() {
    int i = threadIdx.x;
    if (i < DD/2) {
        double e = (double)(2*i) / (double)DD;
        g_invfreq[i] = (float)(1.0 / pow(10000.0, e));
    }
}

// ===========================================================================
// Merged preprocessing (unchanged from R14)
// ===========================================================================
__device__ __forceinline__ void transpose_tile32(
    const float* __restrict__ W, __half* __restrict__ Th,
    int K, int N, int bx, int by, float (*tile)[33])
{
    int tid = threadIdx.x;
    int n0 = bx*32, k0 = by*32;
    int tx = tid & 31, ty = tid >> 5;
    #pragma unroll
    for (int r = 0; r < 4; r++)
        tile[ty + r*8][tx] = W[(size_t)(k0 + ty + r*8)*N + n0 + tx];
    __syncthreads();
    int kx = (tid & 15)*2, ny = tid >> 4;
    #pragma unroll
    for (int r = 0; r < 2; r++) {
        int nn = ny + r*16;
        __half2 h = __floats2half2_rn(tile[kx][nn], tile[kx+1][nn]);
        *(__half2*)(Th + (size_t)(n0 + nn)*K + k0 + kx) = h;
    }
}

#define PREP_BLOCKS (8192 + 12288 + 4096)

__global__ __launch_bounds__(256)
void prep_kernel(const float* __restrict__ x,
                 const float* __restrict__ w_qkv,
                 const float* __restrict__ w_out)
{
    __shared__ float tile[32][33];
    int bid = blockIdx.x;
    if (bid < 8192) {
        int i = (bid*256 + threadIdx.x)*4;
        float4 v = *(const float4*)(x + i);
        *(__half2*)(g_xh + i)     = __floats2half2_rn(v.x, v.y);
        *(__half2*)(g_xh + i + 2) = __floats2half2_rn(v.z, v.w);
    } else if (bid < 8192 + 12288) {
        int lb = bid - 8192;
        transpose_tile32(w_qkv, g_wqt_h, CC, N_QKV, lb % 192, lb / 192, tile);
    } else {
        int lb = bid - 20480;
        transpose_tile32(w_out, g_wot_h, CC, CC, lb % 64, lb / 64, tile);
    }
}

// ===========================================================================
// HMMA fp16 GEMM, 3-stage cp.async pipeline (unchanged from R14).
// ===========================================================================
#define KC 64
#define GT_B 16384
#define STAGE_B (2*GT_B)
#define GH_SMEM (3*STAGE_B)

template<int PERM>
__global__ __launch_bounds__(256, 2)
void gemm_hmma_kernel(const __half* __restrict__ Ah,
                      const __half* __restrict__ Bh,
                      float* __restrict__ C, int M, int N, int K)
{
    extern __shared__ char sm[];
    const uint32_t sbase = smem_u32(sm);

    const int tid  = threadIdx.x;
    const int wid  = tid >> 5;
    const int lane = tid & 31;
    const int wm = wid >> 2;
    const int wn = wid & 3;
    const int bm = blockIdx.y * 128;
    const int bn = blockIdx.x * 128;

    const __half* srcs[2] = { Ah + (size_t)bm*K, Bh + (size_t)bn*K };

    const int aRowB = wm*64 + (lane & 7) + ((lane >> 3) & 1)*8;
    const int aCH   = lane >> 4;
    const int bRowB = wn*32 + ((lane >> 4) & 1)*8 + (lane & 7);
    const int bCH   = (lane >> 3) & 1;

    float acc[4][4][4];
    #pragma unroll
    for (int mt = 0; mt < 4; mt++)
        #pragma unroll
        for (int nt = 0; nt < 4; nt++)
            #pragma unroll
            for (int e = 0; e < 4; e++) acc[mt][nt][e] = 0.f;

    auto load_stage = [&](int buf, int kc) {
        uint32_t stg = sbase + buf*STAGE_B;
        #pragma unroll
        for (int t = 0; t < 2; t++) {
            const __half* sp = srcs[t] + kc*KC;
            uint32_t db = stg + t*GT_B;
            #pragma unroll
            for (int e = 0; e < 4; e++) {
                int idx = e*256 + tid;
                int row = idx >> 3, u = idx & 7;
                uint32_t d = db + row*128 + ((u ^ (row & 7))*16);
                CP_ASYNC16(d, sp + (size_t)row*K + u*8);
            }
        }
    };

    const int nch = K / KC;
    load_stage(0, 0);
    CP_COMMIT();
    load_stage(1, 1);
    CP_COMMIT();

    for (int c = 0; c < nch; c++) {
        if (c + 2 < nch) {
            load_stage((c+2) % 3, c+2);
            CP_COMMIT();
            CP_WAIT(2);
        } else if (c + 1 < nch) {
            CP_WAIT(1);
        } else {
            CP_WAIT(0);
        }
        __syncthreads();

        const uint32_t stg = sbase + (c % 3)*STAGE_B;

        #pragma unroll
        for (int ks = 0; ks < 4; ks++) {
            uint32_t ah[4][4], bh[2][4];
            #pragma unroll
            for (int mt = 0; mt < 4; mt++) {
                int r = aRowB + mt*16;
                uint32_t off = r*128 + (((ks*2 + aCH) ^ (r & 7))*16);
                ldsm4(ah[mt], stg + off);
            }
            #pragma unroll
            for (int nt2 = 0; nt2 < 2; nt2++) {
                int r = bRowB + nt2*16;
                uint32_t off = r*128 + (((ks*2 + bCH) ^ (r & 7))*16);
                ldsm4(bh[nt2], stg + GT_B + off);
            }
            #pragma unroll
            for (int mt = 0; mt < 4; mt++) {
                #pragma unroll
                for (int nt = 0; nt < 4; nt++) {
                    const uint32_t* bhp = &bh[nt >> 1][(nt & 1)*2];
                    mma_f16(acc[mt][nt], ah[mt], bhp);
                }
            }
        }
        __syncthreads();
    }

    if (PERM) {
        const int mat = bn >> 11;
        const int h   = (bn & 2047) >> 7;
        const int b   = bm >> 11;
        __half* dst = (mat == 0) ? g_qpre : (mat == 1) ? g_kpre : g_vh;
        #pragma unroll
        for (int mt = 0; mt < 4; mt++) {
            #pragma unroll
            for (int nt = 0; nt < 4; nt++) {
                int r0 = bm + wm*64 + mt*16 + (lane >> 2);
                int t  = r0 & (TT-1);
                int cl = wn*32 + nt*8 + (lane & 3)*2;
                size_t o = (((size_t)(b*HH + h))*TT + t)*DD + cl;
                *(__half2*)(dst + o) =
                    __floats2half2_rn(acc[mt][nt][0], acc[mt][nt][1]);
                *(__half2*)(dst + o + 8*DD) =
                    __floats2half2_rn(acc[mt][nt][2], acc[mt][nt][3]);
            }
        }
    } else {
        #pragma unroll
        for (int mt = 0; mt < 4; mt++) {
            #pragma unroll
            for (int nt = 0; nt < 4; nt++) {
                int r0 = bm + wm*64 + mt*16 + (lane >> 2);
                int c0 = bn + wn*32 + nt*8 + (lane & 3)*2;
                *(float2*)(C + (size_t)r0*N + c0) =
                    make_float2(acc[mt][nt][0], acc[mt][nt][1]);
                *(float2*)(C + (size_t)(r0+8)*N + c0) =
                    make_float2(acc[mt][nt][2], acc[mt][nt][3]);
            }
        }
    }
}

// ===========================================================================
// RoPE on K only (q rope fused into attention)
// ===========================================================================
__global__ __launch_bounds__(256)
void rope_kernel()
{
    int idx = blockIdx.x*256 + threadIdx.x;
    int d2 = (idx & 31)*2;
    int t  = (idx >> 5) & (TT-1);
    int bh = idx >> 16;

    float sn0, cs0, sn1, cs1;
    sincosf((float)t * g_invfreq[d2],   &sn0, &cs0);
    sincosf((float)t * g_invfreq[d2+1], &sn1, &cs1);

    size_t o = ((size_t)bh*TT + t)*DD + d2;

    float2 lo = __half22float2(*(const __half2*)(g_kpre + o));
    float2 up = __half22float2(*(const __half2*)(g_kpre + o + 64));
    *(__half2*)(g_kh + o)      = __floats2half2_rn(lo.x*cs0 - up.x*sn0,
                                                   lo.y*cs1 - up.y*sn1);
    *(__half2*)(g_kh + o + 64) = __floats2half2_rn(up.x*cs0 + lo.x*sn0,
                                                   up.y*cs1 + lo.y*sn1);
}

// ===========================================================================
// HMMA fp16 flash attention. AK=128, 8 warps x 16 q-rows.
// Q loaded pre-rope, rotated in smem (bit-identical to the old rope kernel).
// Sub-tile causal skipping at 16-key granularity in S and PV phases.
// Smem: Q 32KB + 2 stages x 64KB (K 32 + V 32) = 160KB.
// ===========================================================================
#define AQ 128
#define AK 128
#define SM_Q 32768
#define STG_SZ 65536
#define ATT_SMEM (SM_Q + 2*STG_SZ)   // 163840

__global__ __launch_bounds__(256, 1)
void attn_hmma_kernel()
{
    extern __shared__ char sm[];
    const uint32_t sb = smem_u32(sm);
    const int tid = threadIdx.x, wid = tid >> 5, lane = tid & 31;

    const int qt  = (TT/AQ - 1) - blockIdx.x;
    const int bh  = blockIdx.y;
    const int qt0 = qt * AQ;
    const size_t base = (size_t)bh * TT * DD;
    const __half *qpp = g_qpre + base;
    const __half *khp = g_kh + base;
    const __half *vhp = g_vh + base;

    // Q tile (pre-rope) into smem, group 0 with stage 0
    #pragma unroll
    for (int e = 0; e < 8; e++) {
        int idx = e*256 + tid;
        int r   = (idx >> 4) & 127;
        int ug  = idx & 15;
        int h2 = ug >> 3, u = ug & 7;
        uint32_t dst = sb + h2*16384 + r*128 + ((u ^ (r & 7))*16);
        CP_ASYNC16(dst, qpp + (size_t)(qt0 + r)*DD + ug*8);
    }

    const int nch = qt + 1;   // chunks of 128 keys

    auto load_stage = [&](int buf, int j0) {
        uint32_t stg = sb + SM_Q + buf*STG_SZ;
        #pragma unroll
        for (int e = 0; e < 8; e++) {       // K: 128 rows x 16 units
            int idx = e*256 + tid;
            int r   = (idx >> 4) & 127;
            int ug  = idx & 15;
            int h2 = ug >> 3, u = ug & 7;
            uint32_t dst = stg + h2*16384 + r*128 + ((u ^ (r & 7))*16);
            CP_ASYNC16(dst, khp + (size_t)(j0 + r)*DD + ug*8);
        }
        #pragma unroll
        for (int e = 0; e < 8; e++) {       // V
            int idx = e*256 + tid;
            int r   = (idx >> 4) & 127;
            int ug  = idx & 15;
            int h2 = ug >> 3, u = ug & 7;
            uint32_t dst = stg + 32768 + h2*16384 + r*128 + ((u ^ (r & 7))*16);
            CP_ASYNC16(dst, vhp + (size_t)(j0 + r)*DD + ug*8);
        }
    };

    load_stage(0, 0);
    CP_COMMIT();
    if (nch > 1) { load_stage(1, AK); CP_COMMIT(); }

    const int rowblk = (wid < 4) ? wid : (11 - wid);
    const int wrow0 = rowblk * 16;
    const int gq0 = qt0 + wrow0;
    const int wlimit = gq0 + 15;

    float yac[16][4];
    #pragma unroll
    for (int nf = 0; nf < 16; nf++)
        #pragma unroll
        for (int e = 0; e < 4; e++) yac[nf][e] = 0.f;
    float mi[2] = {-1e30f, -1e30f}, li[2] = {0.f, 0.f};

    uint32_t Qfrag[2][4][4];

    const float scale = 0.08838834764831845f;

    for (int c = 0; c < nch; c++) {
        const int j0 = c * AK;

        if (c + 1 < nch) { CP_WAIT(1); } else { CP_WAIT(0); }
        __syncthreads();

        if (c == 0) {
            // ---- fused Q rope in smem (bit-identical to rope_kernel) ----
            {
                int r  = tid >> 1;             // 0..127
                int pb = (tid & 1) * 16;       // pair block
                int t  = qt0 + r;
                #pragma unroll
                for (int i = 0; i < 16; i++) {
                    int d = (pb + i) * 2;      // 0..62
                    int u = d >> 3;
                    uint32_t off = r*128 + ((u ^ (r & 7))*16) + (d & 7)*2;
                    __half2* plo = (__half2*)(sm + off);
                    __half2* pup = (__half2*)(sm + 16384 + off);
                    float2 lo = __half22float2(*plo);
                    float2 up = __half22float2(*pup);
                    float sn0, cs0, sn1, cs1;
                    sincosf((float)t * g_invfreq[d],   &sn0, &cs0);
                    sincosf((float)t * g_invfreq[d+1], &sn1, &cs1);
                    *plo = __floats2half2_rn(lo.x*cs0 - up.x*sn0,
                                             lo.y*cs1 - up.y*sn1);
                    *pup = __floats2half2_rn(up.x*cs0 + lo.x*sn0,
                                             up.y*cs1 + lo.y*sn1);
                }
            }
            __syncthreads();
            // ---- hoist Q fragments ----
            #pragma unroll
            for (int kh2 = 0; kh2 < 2; kh2++) {
                uint32_t qb = sb + kh2*16384;
                #pragma unroll
                for (int ks = 0; ks < 4; ks++) {
                    int ar = wrow0 + (lane & 7) + ((lane >> 3) & 1)*8;
                    int au = ks*2 + (lane >> 4);
                    uint32_t aoff = ar*128 + ((au ^ (ar & 7))*16);
                    ldsm4(Qfrag[kh2][ks], qb + aoff);
                }
            }
        }

        const uint32_t stg = sb + SM_Q + (c & 1)*STG_SZ;

        if (j0 < gq0 + 16) {
            float sa[16][4];
            #pragma unroll
            for (int nf = 0; nf < 16; nf++)
                #pragma unroll
                for (int e = 0; e < 4; e++) sa[nf][e] = 0.f;

            // ---- S = Q.K^T with 16-key sub-tile skipping ----
            #pragma unroll
            for (int kh2 = 0; kh2 < 2; kh2++) {
                uint32_t kb = stg + kh2*16384;
                #pragma unroll
                for (int ks = 0; ks < 4; ks++) {
                    int br_ = ((lane >> 4) & 1)*8 + (lane & 7);
                    int bu  = ks*2 + ((lane >> 3) & 1);
                    #pragma unroll
                    for (int nb = 0; nb < 8; nb++) {
                        if (j0 + nb*16 <= wlimit) {
                            int r = br_ + nb*16;
                            uint32_t boff = r*128 + ((bu ^ (r & 7))*16);
                            uint32_t Kh4[4];
                            ldsm4(Kh4, kb + boff);
                            mma_f16(sa[2*nb],   Qfrag[kh2][ks], Kh4);
                            mma_f16(sa[2*nb+1], Qfrag[kh2][ks], Kh4+2);
                        }
                    }
                }
            }

            #pragma unroll
            for (int nf = 0; nf < 16; nf++)
                #pragma unroll
                for (int e = 0; e < 4; e++) sa[nf][e] *= scale;
            if (j0 + 127 > gq0) {
                #pragma unroll
                for (int nf = 0; nf < 16; nf++)
                    #pragma unroll
                    for (int e = 0; e < 4; e++) {
                        int row = gq0 + (lane >> 2) + (e >> 1)*8;
                        int col = j0 + nf*8 + 2*(lane & 3) + (e & 1);
                        if (col > row) sa[nf][e] = -1e30f;
                    }
            }

            // ---- online softmax ----
            #pragma unroll
            for (int rh = 0; rh < 2; rh++) {
                float m = -1e30f;
                #pragma unroll
                for (int nf = 0; nf < 16; nf++)
                    m = fmaxf(m, fmaxf(sa[nf][rh*2], sa[nf][rh*2+1]));
                m = fmaxf(m, __shfl_xor_sync(0xffffffffu, m, 1));
                m = fmaxf(m, __shfl_xor_sync(0xffffffffu, m, 2));
                float mnew = fmaxf(mi[rh], m);
                float corr = __expf(mi[rh] - mnew);
                float rs = 0.f;
                #pragma unroll
                for (int nf = 0; nf < 16; nf++) {
                    float p0 = __expf(sa[nf][rh*2]   - mnew);
                    float p1 = __expf(sa[nf][rh*2+1] - mnew);
                    sa[nf][rh*2] = p0; sa[nf][rh*2+1] = p1;
                    rs += p0 + p1;
                }
                rs += __shfl_xor_sync(0xffffffffu, rs, 1);
                rs += __shfl_xor_sync(0xffffffffu, rs, 2);
                li[rh] = li[rh]*corr + rs;
                mi[rh] = mnew;
                #pragma unroll
                for (int nf = 0; nf < 16; nf++) {
                    yac[nf][rh*2]   *= corr;
                    yac[nf][rh*2+1] *= corr;
                }
            }

            // ---- Y += P.V with 16-key slice skipping ----
            const uint32_t vb = stg + 32768;
            #pragma unroll
            for (int ks = 0; ks < 8; ks++) {
                if (j0 + ks*16 <= wlimit) {
                    uint32_t pH[4];
                    #pragma unroll
                    for (int q = 0; q < 4; q++) {
                        int f = 2*ks + (q >> 1);
                        int o = (q & 1)*2;
                        __half2 hp;
                        hp.x = __float2half(sa[f][o]);
                        hp.y = __float2half(sa[f][o+1]);
                        pH[q] = *(uint32_t*)&hp;
                    }
                    #pragma unroll
                    for (int db = 0; db < 8; db++) {
                        int m4 = lane >> 3;
                        int j = ks*16 + (m4 & 1)*8 + (lane & 7);
                        int un = (db & 3)*2 + (m4 >> 1);
                        uint32_t off = (db >> 2)*16384 + j*128 + ((un ^ (j & 7))*16);
                        uint32_t Vh4[4];
                        ldsm4t(Vh4, vb + off);
                        mma_f16(yac[db*2],   pH, Vh4);
                        mma_f16(yac[db*2+1], pH, Vh4+2);
                    }
                }
            }
        }

        __syncthreads();
        if (c + 2 < nch) { load_stage(c & 1, (c+2)*AK); CP_COMMIT(); }
    }

    // epilogue: normalize, write fp16 [B,T,C]
    const int b = bh >> 4, h = bh & 15;
    #pragma unroll
    for (int rh = 0; rh < 2; rh++) {
        float inv = 1.f / li[rh];
        int t = gq0 + (lane >> 2) + rh*8;
        size_t rowo = ((size_t)(b*TT + t))*CC + h*DD;
        #pragma unroll
        for (int nf = 0; nf < 16; nf++) {
            int col = nf*8 + 2*(lane & 3);
            __half2 hp;
            hp.x = __float2half(yac[nf][rh*2]*inv);
            hp.y = __float2half(yac[nf][rh*2+1]*inv);
            *(__half2*)(g_yh + rowo + col) = hp;
        }
    }
}

// ===========================================================================
extern "C" void kernel_launch(void* const* d_in, const int* in_sizes, int n_in,
                              void* d_out, int out_size)
{
    const float* x     = (const float*)d_in[0];
    const float* w_qkv = (const float*)d_in[1];
    const float* w_out = (const float*)d_in[2];
    float* out = (float*)d_out;

    __half *xh, *yh, *wqh, *woh;
    cudaGetSymbolAddress((void**)&xh, g_xh);
    cudaGetSymbolAddress((void**)&yh, g_yh);
    cudaGetSymbolAddress((void**)&wqh, g_wqt_h);
    cudaGetSymbolAddress((void**)&woh, g_wot_h);

    static int attr_set = 0;
    if (!attr_set) {
        cudaFuncSetAttribute(gemm_hmma_kernel<0>,
                             cudaFuncAttributeMaxDynamicSharedMemorySize, GH_SMEM);
        cudaFuncSetAttribute(gemm_hmma_kernel<1>,
                             cudaFuncAttributeMaxDynamicSharedMemorySize, GH_SMEM);
        cudaFuncSetAttribute(attn_hmma_kernel,
                             cudaFuncAttributeMaxDynamicSharedMemorySize, ATT_SMEM);
        attr_set = 1;
    }

    init_invfreq_kernel<<<1, 64>>>();

    // merged preprocessing: convert x + transpose both weights
    prep_kernel<<<PREP_BLOCKS, 256>>>(x, w_qkv, w_out);

    // qkv = x @ w_qkv, epilogue writes permuted q/k (pre-rope) and final v
    gemm_hmma_kernel<1><<<dim3(N_QKV/128, MM/128), 256, GH_SMEM>>>(
        xh, wqh, nullptr, MM, N_QKV, CC);

    // RoPE on K only (Q rope fused into attention)
    rope_kernel<<<(BB*HH*TT*32)/256, 256>>>();

    // fp16 flash attention -> yh [B,T,C]
    attn_hmma_kernel<<<dim3(TT/AQ, BB*HH), 256, ATT_SMEM>>>();

    // out = y @ w_out  (fp32 output)
    gemm_hmma_kernel<0><<<dim3(CC/128, MM/128), 256, GH_SMEM>>>(
        yh, woh, out, MM, CC, CC);
}

// round 16
// speedup vs baseline: 1.0945x; 1.0945x over previous
#include <cuda_runtime.h>
#include <cuda_fp16.h>
#include <cstdint>
#include <math.h>

// Problem constants
#define BB 2
#define TT 2048
#define CC 2048
#define HH 16
#define DD 128
#define MM (BB*TT)          // 4096
#define N_QKV (3*CC)        // 6144

// Scratch (static device globals; no runtime allocation allowed)
__device__ float g_invfreq[DD/2];

// fp16 operands
__device__ __half g_xh[(size_t)MM * CC];
__device__ __half g_yh[(size_t)MM * CC];         // attention out [B,T,C]
__device__ __half g_wqt_h[(size_t)N_QKV * CC];   // w_qkv^T [N,K]
__device__ __half g_wot_h[(size_t)CC * CC];      // w_out^T
__device__ __half g_qpre[(size_t)MM * CC];       // pre-rope q [B,H,T,D]
__device__ __half g_kpre[(size_t)MM * CC];       // pre-rope k [B,H,T,D]
__device__ __half g_kh[(size_t)MM * CC];         // roped k [B,H,T,D]
__device__ __half g_vh[(size_t)MM * CC];         // v (from GEMM1 epilogue)

// ===========================================================================
__device__ __forceinline__ uint32_t smem_u32(const void* p) {
    uint32_t a;
    asm("{ .reg .u64 t; cvta.to.shared.u64 t, %1; cvt.u32.u64 %0, t; }"
        : "=r"(a) : "l"(p));
    return a;
}
#define CP_ASYNC16(dst, src) \
    asm volatile("cp.async.cg.shared.global [%0], [%1], 16;" :: "r"(dst), "l"(src))
#define CP_COMMIT() asm volatile("cp.async.commit_group;" ::: "memory")
#define CP_WAIT(n)  asm volatile("cp.async.wait_group %0;" :: "n"(n) : "memory")

__device__ __forceinline__ void ldsm4(uint32_t* r, uint32_t addr) {
    asm volatile("ldmatrix.sync.aligned.m8n8.x4.shared.b16 {%0,%1,%2,%3}, [%4];"
        : "=r"(r[0]), "=r"(r[1]), "=r"(r[2]), "=r"(r[3]) : "r"(addr));
}
__device__ __forceinline__ void ldsm4t(uint32_t* r, uint32_t addr) {
    asm volatile("ldmatrix.sync.aligned.m8n8.x4.trans.shared.b16 {%0,%1,%2,%3}, [%4];"
        : "=r"(r[0]), "=r"(r[1]), "=r"(r[2]), "=r"(r[3]) : "r"(addr));
}
__device__ __forceinline__ void mma_f16(float* d, const uint32_t* a, const uint32_t* b) {
    asm volatile("mma.sync.aligned.m16n8k16.row.col.f32.f16.f16.f32 "
        "{%0,%1,%2,%3}, {%4,%5,%6,%7}, {%8,%9}, {%0,%1,%2,%3};"
        : "+f"(d[0]), "+f"(d[1]), "+f"(d[2]), "+f"(d[3])
        : "r"(a[0]), "r"(a[1]), "r"(a[2]), "r"(a[3]), "r"(b[0]), "r"(b[1]));
}

// ===========================================================================
__global__ void init_invfreq_kernel() {
    int i = threadIdx.x;
    if (i < DD/2) {
        double e = (double)(2*i) / (double)DD;
        g_invfreq[i] = (float)(1.0 / pow(10000.0, e));
    }
}

// ===========================================================================
// Merged preprocessing (unchanged from R14)
// ===========================================================================
__device__ __forceinline__ void transpose_tile32(
    const float* __restrict__ W, __half* __restrict__ Th,
    int K, int N, int bx, int by, float (*tile)[33])
{
    int tid = threadIdx.x;
    int n0 = bx*32, k0 = by*32;
    int tx = tid & 31, ty = tid >> 5;
    #pragma unroll
    for (int r = 0; r < 4; r++)
        tile[ty + r*8][tx] = W[(size_t)(k0 + ty + r*8)*N + n0 + tx];
    __syncthreads();
    int kx = (tid & 15)*2, ny = tid >> 4;
    #pragma unroll
    for (int r = 0; r < 2; r++) {
        int nn = ny + r*16;
        __half2 h = __floats2half2_rn(tile[kx][nn], tile[kx+1][nn]);
        *(__half2*)(Th + (size_t)(n0 + nn)*K + k0 + kx) = h;
    }
}

#define PREP_BLOCKS (8192 + 12288 + 4096)

__global__ __launch_bounds__(256)
void prep_kernel(const float* __restrict__ x,
                 const float* __restrict__ w_qkv,
                 const float* __restrict__ w_out)
{
    __shared__ float tile[32][33];
    int bid = blockIdx.x;
    if (bid < 8192) {
        int i = (bid*256 + threadIdx.x)*4;
        float4 v = *(const float4*)(x + i);
        *(__half2*)(g_xh + i)     = __floats2half2_rn(v.x, v.y);
        *(__half2*)(g_xh + i + 2) = __floats2half2_rn(v.z, v.w);
    } else if (bid < 8192 + 12288) {
        int lb = bid - 8192;
        transpose_tile32(w_qkv, g_wqt_h, CC, N_QKV, lb % 192, lb / 192, tile);
    } else {
        int lb = bid - 20480;
        transpose_tile32(w_out, g_wot_h, CC, CC, lb % 64, lb / 64, tile);
    }
}

// ===========================================================================
// HMMA fp16 GEMM, 3-stage cp.async pipeline (unchanged from R14).
// ===========================================================================
#define KC 64
#define GT_B 16384
#define STAGE_B (2*GT_B)
#define GH_SMEM (3*STAGE_B)

template<int PERM>
__global__ __launch_bounds__(256, 2)
void gemm_hmma_kernel(const __half* __restrict__ Ah,
                      const __half* __restrict__ Bh,
                      float* __restrict__ C, int M, int N, int K)
{
    extern __shared__ char sm[];
    const uint32_t sbase = smem_u32(sm);

    const int tid  = threadIdx.x;
    const int wid  = tid >> 5;
    const int lane = tid & 31;
    const int wm = wid >> 2;
    const int wn = wid & 3;
    const int bm = blockIdx.y * 128;
    const int bn = blockIdx.x * 128;

    const __half* srcs[2] = { Ah + (size_t)bm*K, Bh + (size_t)bn*K };

    const int aRowB = wm*64 + (lane & 7) + ((lane >> 3) & 1)*8;
    const int aCH   = lane >> 4;
    const int bRowB = wn*32 + ((lane >> 4) & 1)*8 + (lane & 7);
    const int bCH   = (lane >> 3) & 1;

    float acc[4][4][4];
    #pragma unroll
    for (int mt = 0; mt < 4; mt++)
        #pragma unroll
        for (int nt = 0; nt < 4; nt++)
            #pragma unroll
            for (int e = 0; e < 4; e++) acc[mt][nt][e] = 0.f;

    auto load_stage = [&](int buf, int kc) {
        uint32_t stg = sbase + buf*STAGE_B;
        #pragma unroll
        for (int t = 0; t < 2; t++) {
            const __half* sp = srcs[t] + kc*KC;
            uint32_t db = stg + t*GT_B;
            #pragma unroll
            for (int e = 0; e < 4; e++) {
                int idx = e*256 + tid;
                int row = idx >> 3, u = idx & 7;
                uint32_t d = db + row*128 + ((u ^ (row & 7))*16);
                CP_ASYNC16(d, sp + (size_t)row*K + u*8);
            }
        }
    };

    const int nch = K / KC;
    load_stage(0, 0);
    CP_COMMIT();
    load_stage(1, 1);
    CP_COMMIT();

    for (int c = 0; c < nch; c++) {
        if (c + 2 < nch) {
            load_stage((c+2) % 3, c+2);
            CP_COMMIT();
            CP_WAIT(2);
        } else if (c + 1 < nch) {
            CP_WAIT(1);
        } else {
            CP_WAIT(0);
        }
        __syncthreads();

        const uint32_t stg = sbase + (c % 3)*STAGE_B;

        #pragma unroll
        for (int ks = 0; ks < 4; ks++) {
            uint32_t ah[4][4], bh[2][4];
            #pragma unroll
            for (int mt = 0; mt < 4; mt++) {
                int r = aRowB + mt*16;
                uint32_t off = r*128 + (((ks*2 + aCH) ^ (r & 7))*16);
                ldsm4(ah[mt], stg + off);
            }
            #pragma unroll
            for (int nt2 = 0; nt2 < 2; nt2++) {
                int r = bRowB + nt2*16;
                uint32_t off = r*128 + (((ks*2 + bCH) ^ (r & 7))*16);
                ldsm4(bh[nt2], stg + GT_B + off);
            }
            #pragma unroll
            for (int mt = 0; mt < 4; mt++) {
                #pragma unroll
                for (int nt = 0; nt < 4; nt++) {
                    const uint32_t* bhp = &bh[nt >> 1][(nt & 1)*2];
                    mma_f16(acc[mt][nt], ah[mt], bhp);
                }
            }
        }
        __syncthreads();
    }

    if (PERM) {
        const int mat = bn >> 11;
        const int h   = (bn & 2047) >> 7;
        const int b   = bm >> 11;
        __half* dst = (mat == 0) ? g_qpre : (mat == 1) ? g_kpre : g_vh;
        #pragma unroll
        for (int mt = 0; mt < 4; mt++) {
            #pragma unroll
            for (int nt = 0; nt < 4; nt++) {
                int r0 = bm + wm*64 + mt*16 + (lane >> 2);
                int t  = r0 & (TT-1);
                int cl = wn*32 + nt*8 + (lane & 3)*2;
                size_t o = (((size_t)(b*HH + h))*TT + t)*DD + cl;
                *(__half2*)(dst + o) =
                    __floats2half2_rn(acc[mt][nt][0], acc[mt][nt][1]);
                *(__half2*)(dst + o + 8*DD) =
                    __floats2half2_rn(acc[mt][nt][2], acc[mt][nt][3]);
            }
        }
    } else {
        #pragma unroll
        for (int mt = 0; mt < 4; mt++) {
            #pragma unroll
            for (int nt = 0; nt < 4; nt++) {
                int r0 = bm + wm*64 + mt*16 + (lane >> 2);
                int c0 = bn + wn*32 + nt*8 + (lane & 3)*2;
                *(float2*)(C + (size_t)r0*N + c0) =
                    make_float2(acc[mt][nt][0], acc[mt][nt][1]);
                *(float2*)(C + (size_t)(r0+8)*N + c0) =
                    make_float2(acc[mt][nt][2], acc[mt][nt][3]);
            }
        }
    }
}

// ===========================================================================
// RoPE on K only (Q rope fused into attention)
// ===========================================================================
__global__ __launch_bounds__(256)
void rope_kernel()
{
    int idx = blockIdx.x*256 + threadIdx.x;
    int d2 = (idx & 31)*2;
    int t  = (idx >> 5) & (TT-1);
    int bh = idx >> 16;

    float sn0, cs0, sn1, cs1;
    sincosf((float)t * g_invfreq[d2],   &sn0, &cs0);
    sincosf((float)t * g_invfreq[d2+1], &sn1, &cs1);

    size_t o = ((size_t)bh*TT + t)*DD + d2;

    float2 lo = __half22float2(*(const __half2*)(g_kpre + o));
    float2 up = __half22float2(*(const __half2*)(g_kpre + o + 64));
    *(__half2*)(g_kh + o)      = __floats2half2_rn(lo.x*cs0 - up.x*sn0,
                                                   lo.y*cs1 - up.y*sn1);
    *(__half2*)(g_kh + o + 64) = __floats2half2_rn(up.x*cs0 + lo.x*sn0,
                                                   up.y*cs1 + lo.y*sn1);
}

// ===========================================================================
// HMMA fp16 flash attention (R14 structure: AK=64, 3-stage pipeline,
// Q-fragment hoisting) + fused Q rope in smem at c==0 (bit-identical math).
// Smem: Q 32KB + 3 stages x 32KB = 128KB.
// ===========================================================================
#define AQ 128
#define AK 64
#define SM_Q 32768
#define STG_SZ 32768
#define ATT_SMEM (SM_Q + 3*STG_SZ)   // 131072

__global__ __launch_bounds__(256, 1)
void attn_hmma_kernel()
{
    extern __shared__ char sm[];
    const uint32_t sb = smem_u32(sm);
    const int tid = threadIdx.x, wid = tid >> 5, lane = tid & 31;

    const int qt  = (TT/AQ - 1) - blockIdx.x;
    const int bh  = blockIdx.y;
    const int qt0 = qt * AQ;
    const size_t base = (size_t)bh * TT * DD;
    const __half *qpp = g_qpre + base;
    const __half *khp = g_kh + base;
    const __half *vhp = g_vh + base;

    // Q tile (pre-rope) into smem, group 0 with stage 0
    #pragma unroll
    for (int e = 0; e < 8; e++) {
        int idx = e*256 + tid;
        int r   = (idx >> 4) & 127;
        int ug  = idx & 15;
        int h2 = ug >> 3, u = ug & 7;
        uint32_t dst = sb + h2*16384 + r*128 + ((u ^ (r & 7))*16);
        CP_ASYNC16(dst, qpp + (size_t)(qt0 + r)*DD + ug*8);
    }

    const int nch = 2*qt + 2;

    auto load_stage = [&](int buf, int j0) {
        uint32_t stg = sb + SM_Q + buf*STG_SZ;
        #pragma unroll
        for (int e = 0; e < 4; e++) {       // K
            int idx = e*256 + tid;
            int r   = (idx >> 4) & 63;
            int ug  = idx & 15;
            int h2 = ug >> 3, u = ug & 7;
            uint32_t dst = stg + h2*8192 + r*128 + ((u ^ (r & 7))*16);
            CP_ASYNC16(dst, khp + (size_t)(j0 + r)*DD + ug*8);
        }
        #pragma unroll
        for (int e = 0; e < 4; e++) {       // V
            int idx = e*256 + tid;
            int r   = (idx >> 4) & 63;
            int ug  = idx & 15;
            int h2 = ug >> 3, u = ug & 7;
            uint32_t dst = stg + 16384 + h2*8192 + r*128 + ((u ^ (r & 7))*16);
            CP_ASYNC16(dst, vhp + (size_t)(j0 + r)*DD + ug*8);
        }
    };

    load_stage(0, 0);
    CP_COMMIT();
    if (nch > 1) { load_stage(1, AK); CP_COMMIT(); }

    const int rowblk = (wid < 4) ? wid : (11 - wid);
    const int wrow0 = rowblk * 16;
    const int gq0 = qt0 + wrow0;

    float yac[16][4];
    #pragma unroll
    for (int nf = 0; nf < 16; nf++)
        #pragma unroll
        for (int e = 0; e < 4; e++) yac[nf][e] = 0.f;
    float mi[2] = {-1e30f, -1e30f}, li[2] = {0.f, 0.f};

    uint32_t Qfrag[2][4][4];

    const float scale = 0.08838834764831845f;

    for (int c = 0; c < nch; c++) {
        const int j0 = c * AK;

        if (c + 2 < nch) {
            load_stage((c+2) % 3, (c+2)*AK);
            CP_COMMIT();
            CP_WAIT(2);
        } else if (c + 1 < nch) {
            CP_WAIT(1);
        } else {
            CP_WAIT(0);
        }
        __syncthreads();

        if (c == 0) {
            // ---- fused Q rope in smem (bit-identical to old rope path) ----
            {
                int r  = tid >> 1;             // 0..127
                int pb = (tid & 1) * 16;       // pair block
                int t  = qt0 + r;
                #pragma unroll
                for (int i = 0; i < 16; i++) {
                    int d = (pb + i) * 2;      // 0..62
                    int u = d >> 3;
                    uint32_t off = r*128 + ((u ^ (r & 7))*16) + (d & 7)*2;
                    __half2* plo = (__half2*)(sm + off);
                    __half2* pup = (__half2*)(sm + 16384 + off);
                    float2 lo = __half22float2(*plo);
                    float2 up = __half22float2(*pup);
                    float sn0, cs0, sn1, cs1;
                    sincosf((float)t * g_invfreq[d],   &sn0, &cs0);
                    sincosf((float)t * g_invfreq[d+1], &sn1, &cs1);
                    *plo = __floats2half2_rn(lo.x*cs0 - up.x*sn0,
                                             lo.y*cs1 - up.y*sn1);
                    *pup = __floats2half2_rn(up.x*cs0 + lo.x*sn0,
                                             up.y*cs1 + lo.y*sn1);
                }
            }
            __syncthreads();
            // ---- hoist Q fragments ----
            #pragma unroll
            for (int kh2 = 0; kh2 < 2; kh2++) {
                uint32_t qb = sb + kh2*16384;
                #pragma unroll
                for (int ks = 0; ks < 4; ks++) {
                    int ar = wrow0 + (lane & 7) + ((lane >> 3) & 1)*8;
                    int au = ks*2 + (lane >> 4);
                    uint32_t aoff = ar*128 + ((au ^ (ar & 7))*16);
                    ldsm4(Qfrag[kh2][ks], qb + aoff);
                }
            }
        }

        const uint32_t stg = sb + SM_Q + (c % 3)*STG_SZ;

        if (j0 < gq0 + 16) {
            float sa[8][4];
            #pragma unroll
            for (int nf = 0; nf < 8; nf++)
                #pragma unroll
                for (int e = 0; e < 4; e++) sa[nf][e] = 0.f;

            #pragma unroll
            for (int kh2 = 0; kh2 < 2; kh2++) {
                uint32_t kb = stg + kh2*8192;
                #pragma unroll
                for (int ks = 0; ks < 4; ks++) {
                    int br_ = ((lane >> 4) & 1)*8 + (lane & 7);
                    int bu  = ks*2 + ((lane >> 3) & 1);
                    #pragma unroll
                    for (int nb = 0; nb < 4; nb++) {
                        int r = br_ + nb*16;
                        uint32_t boff = r*128 + ((bu ^ (r & 7))*16);
                        uint32_t Kh4[4];
                        ldsm4(Kh4, kb + boff);
                        mma_f16(sa[2*nb],   Qfrag[kh2][ks], Kh4);
                        mma_f16(sa[2*nb+1], Qfrag[kh2][ks], Kh4+2);
                    }
                }
            }

            #pragma unroll
            for (int nf = 0; nf < 8; nf++)
                #pragma unroll
                for (int e = 0; e < 4; e++) sa[nf][e] *= scale;
            if (j0 + 63 > gq0) {
                #pragma unroll
                for (int nf = 0; nf < 8; nf++)
                    #pragma unroll
                    for (int e = 0; e < 4; e++) {
                        int row = gq0 + (lane >> 2) + (e >> 1)*8;
                        int col = j0 + nf*8 + 2*(lane & 3) + (e & 1);
                        if (col > row) sa[nf][e] = -1e30f;
                    }
            }

            #pragma unroll
            for (int rh = 0; rh < 2; rh++) {
                float m = -1e30f;
                #pragma unroll
                for (int nf = 0; nf < 8; nf++)
                    m = fmaxf(m, fmaxf(sa[nf][rh*2], sa[nf][rh*2+1]));
                m = fmaxf(m, __shfl_xor_sync(0xffffffffu, m, 1));
                m = fmaxf(m, __shfl_xor_sync(0xffffffffu, m, 2));
                float mnew = fmaxf(mi[rh], m);
                float corr = __expf(mi[rh] - mnew);
                float rs = 0.f;
                #pragma unroll
                for (int nf = 0; nf < 8; nf++) {
                    float p0 = __expf(sa[nf][rh*2]   - mnew);
                    float p1 = __expf(sa[nf][rh*2+1] - mnew);
                    sa[nf][rh*2] = p0; sa[nf][rh*2+1] = p1;
                    rs += p0 + p1;
                }
                rs += __shfl_xor_sync(0xffffffffu, rs, 1);
                rs += __shfl_xor_sync(0xffffffffu, rs, 2);
                li[rh] = li[rh]*corr + rs;
                mi[rh] = mnew;
                #pragma unroll
                for (int nf = 0; nf < 16; nf++) {
                    yac[nf][rh*2]   *= corr;
                    yac[nf][rh*2+1] *= corr;
                }
            }

            uint32_t pH[4][4];
            #pragma unroll
            for (int j = 0; j < 4; j++) {
                #pragma unroll
                for (int q = 0; q < 4; q++) {
                    int f = 2*j + (q >> 1);
                    int o = (q & 1)*2;
                    __half2 hp;
                    hp.x = __float2half(sa[f][o]);
                    hp.y = __float2half(sa[f][o+1]);
                    pH[j][q] = *(uint32_t*)&hp;
                }
            }

            const uint32_t vb = stg + 16384;
            #pragma unroll
            for (int ks = 0; ks < 4; ks++) {
                #pragma unroll
                for (int db = 0; db < 8; db++) {
                    int m4 = lane >> 3;
                    int j = ks*16 + (m4 & 1)*8 + (lane & 7);
                    int un = (db & 3)*2 + (m4 >> 1);
                    uint32_t off = (db >> 2)*8192 + j*128 + ((un ^ (j & 7))*16);
                    uint32_t Vh4[4];
                    ldsm4t(Vh4, vb + off);
                    mma_f16(yac[db*2],   pH[ks], Vh4);
                    mma_f16(yac[db*2+1], pH[ks], Vh4+2);
                }
            }
        }

        __syncthreads();
    }

    const int b = bh >> 4, h = bh & 15;
    #pragma unroll
    for (int rh = 0; rh < 2; rh++) {
        float inv = 1.f / li[rh];
        int t = gq0 + (lane >> 2) + rh*8;
        size_t rowo = ((size_t)(b*TT + t))*CC + h*DD;
        #pragma unroll
        for (int nf = 0; nf < 16; nf++) {
            int col = nf*8 + 2*(lane & 3);
            __half2 hp;
            hp.x = __float2half(yac[nf][rh*2]*inv);
            hp.y = __float2half(yac[nf][rh*2+1]*inv);
            *(__half2*)(g_yh + rowo + col) = hp;
        }
    }
}

// ===========================================================================
extern "C" void kernel_launch(void* const* d_in, const int* in_sizes, int n_in,
                              void* d_out, int out_size)
{
    const float* x     = (const float*)d_in[0];
    const float* w_qkv = (const float*)d_in[1];
    const float* w_out = (const float*)d_in[2];
    float* out = (float*)d_out;

    __half *xh, *yh, *wqh, *woh;
    cudaGetSymbolAddress((void**)&xh, g_xh);
    cudaGetSymbolAddress((void**)&yh, g_yh);
    cudaGetSymbolAddress((void**)&wqh, g_wqt_h);
    cudaGetSymbolAddress((void**)&woh, g_wot_h);

    static int attr_set = 0;
    if (!attr_set) {
        cudaFuncSetAttribute(gemm_hmma_kernel<0>,
                             cudaFuncAttributeMaxDynamicSharedMemorySize, GH_SMEM);
        cudaFuncSetAttribute(gemm_hmma_kernel<1>,
                             cudaFuncAttributeMaxDynamicSharedMemorySize, GH_SMEM);
        cudaFuncSetAttribute(attn_hmma_kernel,
                             cudaFuncAttributeMaxDynamicSharedMemorySize, ATT_SMEM);
        attr_set = 1;
    }

    init_invfreq_kernel<<<1, 64>>>();

    // merged preprocessing: convert x + transpose both weights
    prep_kernel<<<PREP_BLOCKS, 256>>>(x, w_qkv, w_out);

    // qkv = x @ w_qkv, epilogue writes permuted q/k (pre-rope) and final v
    gemm_hmma_kernel<1><<<dim3(N_QKV/128, MM/128), 256, GH_SMEM>>>(
        xh, wqh, nullptr, MM, N_QKV, CC);

    // RoPE on K only (Q rope fused into attention)
    rope_kernel<<<(BB*HH*TT*32)/256, 256>>>();

    // fp16 flash attention -> yh [B,T,C]
    attn_hmma_kernel<<<dim3(TT/AQ, BB*HH), 256, ATT_SMEM>>>();

    // out = y @ w_out  (fp32 output)
    gemm_hmma_kernel<0><<<dim3(CC/128, MM/128), 256, GH_SMEM>>>(
        yh, woh, out, MM, CC, CC);
}